// round 14
// baseline (speedup 1.0000x reference)
#include <cuda_runtime.h>
#include <cuda_fp16.h>
#include <cuda_bf16.h>

#define BS    32
#define NTOK  512
#define A2LEN 150
#define NTOT  (BS*NTOK)          // 16384
#define NDR   (BS*A2LEN)         // 4800 = 75*64
#define YW    128                // compact y width (120 used + 8 pad)

// ---------------- scratch ----------------------------------------------------
__device__ float g_y  [NTOT * YW];
__device__ float g_yd [3 * NDR * 24];
__device__ __nv_bfloat16 g_yb[NTOT * 64]; // SiLU(b) channels 32..96, bf16
__device__ int   g_src[2 * NTOK * 32];    // [i][r][t]
__device__ __nv_bfloat16 g_wh[208 * 96];  // bf16 Wqv rows: [0,128) compact, [128,208) dense
__device__ __nv_bfloat16 g_wf[96 * 64];   // bf16 fanout W (cols 32..96)
__device__ float g_bias[208];

__device__ __forceinline__ int rowmap(int o) {
    if (o < 40)  return 32 + o;
    if (o < 80)  return 88 + o;
    if (o < 120) return 144 + o;
    return 32;
}
__device__ __forceinline__ int rowmap_all(int o) {   // 0..207 -> Wqv row
    if (o < 128) return rowmap(o);
    int oo = o - 128; if (oo > 71) oo = 71;
    int p = oo / 24, c = oo - p*24;
    return 96*p + 72 + c;
}

// bf16 m16n8k16 MMA, fp32 accumulate
__device__ __forceinline__ void mma16816(float* c,
                                         unsigned a0, unsigned a1,
                                         unsigned a2, unsigned a3,
                                         unsigned b0, unsigned b1) {
    asm volatile(
        "mma.sync.aligned.m16n8k16.row.col.f32.bf16.bf16.f32 "
        "{%0,%1,%2,%3}, {%4,%5,%6,%7}, {%8,%9}, {%0,%1,%2,%3};"
        : "+f"(c[0]), "+f"(c[1]), "+f"(c[2]), "+f"(c[3])
        : "r"(a0), "r"(a1), "r"(a2), "r"(a3), "r"(b0), "r"(b1));
}

__device__ __forceinline__ float silu(float v) {
    return v / (1.0f + __expf(-1.702f * v));
}
__device__ __forceinline__ __half2 shfl_h2(__half2 v, int mask) {
    unsigned u = *(unsigned*)&v;
    u = __shfl_xor_sync(0xffffffffu, u, mask);
    return *(__half2*)&u;
}

#define XS 104    // bf16 smem row stride (qkv tiles)
#define FS 72     // bf16 smem row stride (final tiles, K=64)

// =============== Kernel 0: weight conversions only (14 blocks) ================
__global__ void __launch_bounds__(256) k_pre(const float* __restrict__ W,
                                             const float* __restrict__ Wf) {
    const int blk = blockIdx.x, tid = threadIdx.x;
    if (blk < 13) {
        const int o0 = blk * 16;
#pragma unroll
        for (int j = 0; j < 6; j++) {
            int i = j*256 + tid;
            int o = o0 + i / 96, k = i % 96;
            g_wh[o*96 + k] = __float2bfloat16_rn(W[rowmap_all(o)*97 + k]);
        }
    } else {
        for (int i = tid; i < 96*64; i += 256) {
            int o = i / 64, k = i - o*64;
            g_wf[i] = __float2bfloat16_rn(Wf[o*97 + 32 + k]);
        }
        if (tid < 208) g_bias[tid] = W[rowmap_all(tid)*97 + 96];
    }
}

// =============== Kernel A: GEMMs + prep (459 blocks, 256 thr) =================
__global__ void __launch_bounds__(256, 4) k_gemms(const float* __restrict__ x,
                                                  const int* __restrict__ coo0,
                                                  const int* __restrict__ coo1,
                                                  const int* __restrict__ a2a) {
    extern __shared__ __align__(16) float sm[];
    const int blk = blockIdx.x;
    const int tid = threadIdx.x;

    if (blk < 256) {
        __nv_bfloat16* sX  = (__nv_bfloat16*)sm;     // [64][XS]
        __nv_bfloat16* sWh = sX + 64*XS;             // [128][XS]
        float*         sB  = (float*)(sWh + 128*XS); // [128]
        const int t0 = blk * 64;

        for (int idx = tid; idx < 64*48; idx += 256) {
            int row = idx / 48, c = idx - row*48;
            float2 v = *(const float2*)&x[(t0 + row)*96 + 2*c];
            *(__nv_bfloat162*)&sX[row*XS + 2*c] = __float22bfloat162_rn(v);
        }
        for (int idx = tid; idx < 1536; idx += 256) {
            int row = idx / 12, q = idx - row*12;
            *(uint4*)&sWh[row*XS + q*8] =
                *(const uint4*)&g_wh[row*96 + q*8];
        }
        if (tid < 128) sB[tid] = g_bias[tid];
        __syncthreads();

        const int warp = tid >> 5, lane = tid & 31;
        const int mw = (warp & 3) * 16;
        const int nw = (warp >> 2) * 64;
        const int gr = lane >> 2;
        const int qp = (lane & 3) * 2;

        float acc[8][4];
#pragma unroll
        for (int n = 0; n < 8; n++)
#pragma unroll
            for (int j = 0; j < 4; j++) acc[n][j] = 0.f;

        const __nv_bfloat16* ab = &sX[(mw + gr)*XS + qp];
#pragma unroll
        for (int ks = 0; ks < 6; ks++) {
            const int k0 = ks * 16;
            unsigned a0 = *(const unsigned*)(ab + k0);
            unsigned a1 = *(const unsigned*)(ab + k0 + 8*XS);
            unsigned a2 = *(const unsigned*)(ab + k0 + 8);
            unsigned a3 = *(const unsigned*)(ab + k0 + 8*XS + 8);
#pragma unroll
            for (int n = 0; n < 8; n++) {
                const __nv_bfloat16* bb = &sWh[(nw + n*8 + gr)*XS + k0 + qp];
                unsigned b0 = *(const unsigned*)bb;
                unsigned b1 = *(const unsigned*)(bb + 8);
                mma16816(acc[n], a0, a1, a2, a3, b0, b1);
            }
        }
        const int r0 = t0 + mw + gr;
#pragma unroll
        for (int n = 0; n < 8; n++) {
            int col = nw + n*8 + qp;
            float bb0 = sB[col], bb1 = sB[col + 1];
            *(float2*)&g_y[r0*YW + col] =
                make_float2(acc[n][0] + bb0, acc[n][1] + bb1);
            *(float2*)&g_y[(r0 + 8)*YW + col] =
                make_float2(acc[n][2] + bb0, acc[n][3] + bb1);
        }
    } else if (blk < 331) {
        const int d = blk - 256;                     // 0..74
        __nv_bfloat16* sX  = (__nv_bfloat16*)sm;     // [64][XS]
        __nv_bfloat16* sWh = sX + 64*XS;             // [80][XS]
        float*         sB  = (float*)(sWh + 80*XS);  // [80]
        int*           sRow = (int*)(sB + 80);       // [64]
        const int r0 = d * 64;

        if (tid < 64) {
            int r = r0 + tid;
            int b = r / A2LEN, dd = r - b*A2LEN;
            sRow[tid] = b*NTOK + a2a[dd];
        }
        __syncthreads();
        for (int idx = tid; idx < 64*48; idx += 256) {
            int row = idx / 48, c = idx - row*48;
            float2 v = *(const float2*)&x[sRow[row]*96 + 2*c];
            *(__nv_bfloat162*)&sX[row*XS + 2*c] = __float22bfloat162_rn(v);
        }
        for (int idx = tid; idx < 960; idx += 256) {
            int row = idx / 12, q = idx - row*12;
            *(uint4*)&sWh[row*XS + q*8] =
                *(const uint4*)&g_wh[(128 + row)*96 + q*8];
        }
        if (tid < 80) sB[tid] = g_bias[128 + tid];
        __syncthreads();

        const int warp = tid >> 5, lane = tid & 31;
        const int mw = (warp & 3) * 16;
        const int nw = (warp >> 2) * 40;
        const int gr = lane >> 2;
        const int qp = (lane & 3) * 2;

        float acc[5][4];
#pragma unroll
        for (int n = 0; n < 5; n++)
#pragma unroll
            for (int j = 0; j < 4; j++) acc[n][j] = 0.f;

        const __nv_bfloat16* ab = &sX[(mw + gr)*XS + qp];
#pragma unroll
        for (int ks = 0; ks < 6; ks++) {
            const int k0 = ks * 16;
            unsigned a0 = *(const unsigned*)(ab + k0);
            unsigned a1 = *(const unsigned*)(ab + k0 + 8*XS);
            unsigned a2 = *(const unsigned*)(ab + k0 + 8);
            unsigned a3 = *(const unsigned*)(ab + k0 + 8*XS + 8);
#pragma unroll
            for (int n = 0; n < 5; n++) {
                const __nv_bfloat16* bb = &sWh[(nw + n*8 + gr)*XS + k0 + qp];
                unsigned b0 = *(const unsigned*)bb;
                unsigned b1 = *(const unsigned*)(bb + 8);
                mma16816(acc[n], a0, a1, a2, a3, b0, b1);
            }
        }
        const int rr = r0 + mw + gr;
#pragma unroll
        for (int n = 0; n < 5; n++) {
            int col = nw + n*8 + qp;
            if (col < 72) {
                int p = col / 24, c = col - p*24;
                float bb0 = sB[col], bb1 = sB[col + 1];
                *(float2*)&g_yd[p*(NDR*24) + rr*24 + c] =
                    make_float2(acc[n][0] + bb0, acc[n][1] + bb1);
                *(float2*)&g_yd[p*(NDR*24) + (rr + 8)*24 + c] =
                    make_float2(acc[n][2] + bb0, acc[n][3] + bb1);
            }
        }
    } else if (blk < 395) {
        const int pb = blk - 331;                // 0..63 coo transpose
#pragma unroll
        for (int j = 0; j < 2; j++) {
            int g = pb*512 + j*256 + tid;
            int i = g >> 14;
            int e = g & 16383;
            const int* coo = i ? coo1 : coo0;
            int src = coo[e*3 + 1];
            int tok = e >> 5, r = e & 31;
            g_src[i*16384 + r*512 + tok] = src;
        }
    } else {
        const int zb = blk - 395;                // 0..63 zero g_yb
        uint4 z = make_uint4(0,0,0,0);
#pragma unroll
        for (int j = 0; j < 8; j++)
            *(uint4*)&g_yb[(zb*2048 + j*256 + tid)*8] = z;
    }
}

// =============== Kernel B: attentions + SiLU -> g_yb (320 blocks, 512 thr) ====
// [0,256): sparse — 128 tok x 2 hp x 2 r-chunks, shfl combine
// [256,320): dense — 128 d-rows x 4 h
#define SPLH (NTOK*12)
__global__ void __launch_bounds__(512) k_attn(const int* __restrict__ a2a) {
    extern __shared__ __align__(16) float smf[];
    const int blk = blockIdx.x;
    const int tid = threadIdx.x;

    if (blk < 256) {
        __half* hs = (__half*)smf;               // 48 KB
        const int b    = blk >> 3;
        const int i    = (blk >> 2) & 1;
        const int quar = blk & 3;

        for (int idx = tid; idx < 10240; idx += 512) {
            int p    = idx / 5120;
            int rem  = idx - p*5120;
            int hp   = rem / 2560;
            int rem2 = rem - hp*2560;
            int tok  = rem2 / 5;
            int c    = rem2 - tok*5;
            float2 v = *(const float2*)&g_y[(b*NTOK + tok)*YW + 40 + p*40 + i*20 + hp*10 + 2*c];
            *(__half2*)&hs[(p*2 + hp)*SPLH + tok*12 + 2*c] = __float22half2_rn(v);
        }
        __syncthreads();

        const int t  = quar*128 + (tid >> 2);
        const int hp = (tid >> 1) & 1;
        const int rc = tid & 1;
        const __half* sK = hs + hp*SPLH;
        const __half* sV = hs + (2 + hp)*SPLH;
        const float* qp = &g_y[(b*NTOK + t)*YW + i*20 + hp*10];
        __half2 qh[5];
#pragma unroll
        for (int w = 0; w < 5; w++)
            qh[w] = __floats2half2_rn(qp[2*w], qp[2*w+1]);
        const int* srcp = &g_src[i*16384 + rc*16*512 + t];
        const float scale = 0.44721359549995793f;   // 1/sqrt(5)
        float l0 = 0.f, l1 = 0.f;
        __half2 acc0 = __float2half2_rn(0.f), acc1 = acc0, acc2 = acc0,
                acc3 = acc0, acc4 = acc0;
#pragma unroll 4
        for (int r = 0; r < 16; r++) {
            int base = srcp[r*512] * 12;
            uint2 ka = *(const uint2*)&sK[base];
            uint2 kb = *(const uint2*)&sK[base + 4];
            unsigned int kc = *(const unsigned int*)&sK[base + 8];
            __half2 d0 = __habs2(__hsub2(qh[0], *(const __half2*)&ka.x));
            __half2 d1 = __habs2(__hsub2(qh[1], *(const __half2*)&ka.y));
            __half2 d2 = __habs2(__hsub2(qh[2], *(const __half2*)&kb.x));
            __half2 d3 = __habs2(__hsub2(qh[3], *(const __half2*)&kb.y));
            __half2 d4 = __habs2(__hsub2(qh[4], *(const __half2*)&kc));
            __half2 u = __hadd2(d0, d1);
            __half2 v = __hadd2(d3, d4);
            __half2 uv = __hadd2(__halves2half2(__low2half(u),  __low2half(v)),
                                 __halves2half2(__high2half(u), __high2half(v)));
            __half2 s2 = __hadd2(uv, d2);
            float2 sf = __half22float2(s2);
            float p0 = __expf(-sf.x * scale);
            float p1 = __expf(-sf.y * scale);
            l0 += p0; l1 += p1;
            __half h0 = __float2half_rn(p0), h1 = __float2half_rn(p1);
            __half2 pp00 = __halves2half2(h0, h0);
            __half2 pp01 = __halves2half2(h0, h1);
            __half2 pp11 = __halves2half2(h1, h1);
            uint2 va = *(const uint2*)&sV[base];
            uint2 vb = *(const uint2*)&sV[base + 4];
            unsigned int vc = *(const unsigned int*)&sV[base + 8];
            acc0 = __hfma2(pp00, *(const __half2*)&va.x, acc0);
            acc1 = __hfma2(pp00, *(const __half2*)&va.y, acc1);
            acc2 = __hfma2(pp01, *(const __half2*)&vb.x, acc2);
            acc3 = __hfma2(pp11, *(const __half2*)&vb.y, acc3);
            acc4 = __hfma2(pp11, *(const __half2*)&vc,   acc4);
        }
        // combine r-chunks (adjacent lanes, bit 0)
        l0 += __shfl_xor_sync(0xffffffffu, l0, 1);
        l1 += __shfl_xor_sync(0xffffffffu, l1, 1);
        acc0 = __hadd2(acc0, shfl_h2(acc0, 1));
        acc1 = __hadd2(acc1, shfl_h2(acc1, 1));
        acc2 = __hadd2(acc2, shfl_h2(acc2, 1));
        acc3 = __hadd2(acc3, shfl_h2(acc3, 1));
        acc4 = __hadd2(acc4, shfl_h2(acc4, 1));
        if (rc == 0) {
            float inv0 = 1.0f / l0, inv1 = 1.0f / l1;
            float2 f0 = __half22float2(acc0);
            float2 f1 = __half22float2(acc1);
            float2 f2 = __half22float2(acc2);
            float2 f3 = __half22float2(acc3);
            float2 f4 = __half22float2(acc4);
            float o_[10] = { f0.x*inv0, f0.y*inv0, f1.x*inv0, f1.y*inv0,
                             f2.x*inv0, f2.y*inv1, f3.x*inv1, f3.y*inv1,
                             f4.x*inv1, f4.y*inv1 };
            __nv_bfloat16* op = &g_yb[(b*NTOK + t)*64 + i*20 + hp*10];
#pragma unroll
            for (int w = 0; w < 5; w++)
                *(__nv_bfloat162*)&op[2*w] =
                    __float22bfloat162_rn(make_float2(silu(o_[2*w]), silu(o_[2*w+1])));
        }
    } else {
        const int idx = blk - 256;               // 0..63
        const int b   = idx & 31;
        const int d0  = (idx >> 5) * 128;        // 0 or 128
        float* sK = smf;
        float* sV = smf + A2LEN*24;
        const int P = NDR * 24;
        for (int j = tid; j < A2LEN*24; j += 512) {
            sK[j] = g_yd[P   + b*A2LEN*24 + j];
            sV[j] = g_yd[2*P + b*A2LEN*24 + j];
        }
        __syncthreads();
        const int dl = tid >> 2, h = tid & 3;
        const int d = d0 + dl;
        if (d >= A2LEN) return;
        const float* qp = &g_yd[(b*A2LEN + d)*24 + h*6];
        float q[6];
#pragma unroll
        for (int w = 0; w < 6; w++) q[w] = qp[w];
        const float scale = 0.4082482904638631f;    // 1/sqrt(6)
        float l = 0.f;
        float acc[6] = {0.f,0.f,0.f,0.f,0.f,0.f};
#pragma unroll 2
        for (int s = 0; s < A2LEN; s++) {
            const float* kp = &sK[s*24 + h*6];
            float2 ka = *(const float2*)kp;
            float2 kb = *(const float2*)(kp + 2);
            float2 kc = *(const float2*)(kp + 4);
            float ds = fabsf(q[0]-ka.x) + fabsf(q[1]-ka.y) + fabsf(q[2]-kb.x)
                     + fabsf(q[3]-kb.y) + fabsf(q[4]-kc.x) + fabsf(q[5]-kc.y);
            float p = __expf(-ds * scale);
            l += p;
            const float* vp = &sV[s*24 + h*6];
            float2 va = *(const float2*)vp;
            float2 vb = *(const float2*)(vp + 2);
            float2 vc = *(const float2*)(vp + 4);
            acc[0] += p*va.x; acc[1] += p*va.y; acc[2] += p*vb.x;
            acc[3] += p*vb.y; acc[4] += p*vc.x; acc[5] += p*vc.y;
        }
        {
            float ds = fabsf(q[0]) + fabsf(q[1]) + fabsf(q[2])
                     + fabsf(q[3]) + fabsf(q[4]) + fabsf(q[5]);
            l += __expf(-ds * scale);
        }
        float inv = 1.0f / l;
        int row = b*NTOK + a2a[d];
        __nv_bfloat16* op = &g_yb[row*64 + 40 + h*6];
#pragma unroll
        for (int w = 0; w < 3; w++)
            *(__nv_bfloat162*)&op[2*w] =
                __float22bfloat162_rn(make_float2(silu(acc[2*w]*inv),
                                                  silu(acc[2*w+1]*inv)));
    }
}

// =============== Kernel C: out = x + yb @ Wf^T + bias (bf16 MMA, 512 blks) ====
__global__ void __launch_bounds__(256) k_final(const float* __restrict__ x,
                                               const float* __restrict__ Wf,
                                               float* __restrict__ out) {
    __shared__ __align__(16) __nv_bfloat16 sY [32*FS];
    __shared__ __align__(16) __nv_bfloat16 sWf[96*FS];
    __shared__ __align__(16) float sB[96];
    const int t0 = blockIdx.x * 32;
    const int tid = threadIdx.x;

    {
        int t = tid >> 3, q = tid & 7;
        *(uint4*)&sY[t*FS + q*8] = *(const uint4*)&g_yb[(t0 + t)*64 + q*8];
    }
    for (int idx = tid; idx < 768; idx += 256) {
        int o = idx / 8, q = idx - o*8;
        *(uint4*)&sWf[o*FS + q*8] = *(const uint4*)&g_wf[o*64 + q*8];
    }
    if (tid < 96) sB[tid] = Wf[tid*97 + 96];
    __syncthreads();

    const int warp = tid >> 5, lane = tid & 31;
    const int mw = (warp & 1) * 16;
    const int nw = (warp >> 1) * 24;
    const int gr = lane >> 2;
    const int qp = (lane & 3) * 2;

    float acc[3][4];
#pragma unroll
    for (int n = 0; n < 3; n++)
#pragma unroll
        for (int j = 0; j < 4; j++) acc[n][j] = 0.f;

    const __nv_bfloat16* ab = &sY[(mw + gr)*FS + qp];
#pragma unroll
    for (int ks = 0; ks < 4; ks++) {
        const int k0 = ks * 16;
        unsigned a0 = *(const unsigned*)(ab + k0);
        unsigned a1 = *(const unsigned*)(ab + k0 + 8*FS);
        unsigned a2 = *(const unsigned*)(ab + k0 + 8);
        unsigned a3 = *(const unsigned*)(ab + k0 + 8*FS + 8);
#pragma unroll
        for (int n = 0; n < 3; n++) {
            const __nv_bfloat16* bb = &sWf[(nw + n*8 + gr)*FS + k0 + qp];
            unsigned b0 = *(const unsigned*)bb;
            unsigned b1 = *(const unsigned*)(bb + 8);
            mma16816(acc[n], a0, a1, a2, a3, b0, b1);
        }
    }
    const int r0 = t0 + mw + gr;
#pragma unroll
    for (int n = 0; n < 3; n++) {
        int col = nw + n*8 + qp;
        float bb0 = sB[col], bb1 = sB[col + 1];
        float2 x0 = *(const float2*)&x[r0*96 + col];
        float2 x1 = *(const float2*)&x[(r0 + 8)*96 + col];
        *(float2*)&out[r0*96 + col] =
            make_float2(acc[n][0] + bb0 + x0.x, acc[n][1] + bb1 + x0.y);
        *(float2*)&out[(r0 + 8)*96 + col] =
            make_float2(acc[n][2] + bb0 + x1.x, acc[n][3] + bb1 + x1.y);
    }
}

// ---------------- launch -------------------------------------------------------
extern "C" void kernel_launch(void* const* d_in, const int* in_sizes, int n_in,
                              void* d_out, int out_size) {
    const float* x    = (const float*)d_in[0];
    const float* wqv  = (const float*)d_in[1];
    const float* wf   = (const float*)d_in[2];
    const int*   coo0 = (const int*)d_in[3];
    const int*   coo1 = (const int*)d_in[4];
    const int*   a2a  = (const int*)d_in[5];
    float*       out  = (float*)d_out;
    (void)in_sizes; (void)n_in; (void)out_size;

    const int smemA = (64*XS + 128*XS) * 2 + 128 * 4;        // 40448
    const int smemB = 4 * SPLH * sizeof(__half);             // 49152
    static int inited = 0;
    if (!inited) {
        cudaFuncSetAttribute(k_gemms, cudaFuncAttributeMaxDynamicSharedMemorySize, smemA);
        cudaFuncSetAttribute(k_attn,  cudaFuncAttributeMaxDynamicSharedMemorySize, smemB);
        inited = 1;
    }

    k_pre  <<<14, 256>>>(wqv, wf);
    k_gemms<<<459, 256, smemA>>>(x, coo0, coo1, a2a);
    k_attn <<<320, 512, smemB>>>(a2a);
    k_final<<<512, 256>>>(x, wf, out);
}

// round 15
// speedup vs baseline: 1.2616x; 1.2616x over previous
#include <cuda_runtime.h>
#include <cuda_fp16.h>
#include <cuda_bf16.h>

#define BS    32
#define NTOK  512
#define A2LEN 150
#define NTOT  (BS*NTOK)          // 16384
#define NDR   (BS*A2LEN)         // 4800 = 75*64
#define YW    40                 // g_y now holds q channels only
#define SPLH (NTOK*12)           // halves per (plane,hp) tile = 6144

// ---------------- scratch ----------------------------------------------------
__device__ float g_y  [NTOT * YW];        // q compact channels (fp32)
__device__ __half g_kvh[64 * 4 * SPLH];   // K/V fp16: [(b,i)][p*2+hp][tok][12]
__device__ float g_yd [3 * NDR * 24];
__device__ __nv_bfloat16 g_yb[NTOT * 64]; // SiLU(b) channels 32..96, bf16
__device__ int   g_src[2 * NTOK * 32];    // [i][r][t]
__device__ __nv_bfloat16 g_wh[208 * 96];  // bf16 Wqv rows: [0,128) compact, [128,208) dense
__device__ __nv_bfloat16 g_wf[96 * 64];   // bf16 fanout W (cols 32..96)
__device__ float g_bias[208];

__device__ __forceinline__ int rowmap(int o) {
    if (o < 40)  return 32 + o;
    if (o < 80)  return 88 + o;
    if (o < 120) return 144 + o;
    return 32;
}
__device__ __forceinline__ int rowmap_all(int o) {   // 0..207 -> Wqv row
    if (o < 128) return rowmap(o);
    int oo = o - 128; if (oo > 71) oo = 71;
    int p = oo / 24, c = oo - p*24;
    return 96*p + 72 + c;
}

// bf16 m16n8k16 MMA, fp32 accumulate
__device__ __forceinline__ void mma16816(float* c,
                                         unsigned a0, unsigned a1,
                                         unsigned a2, unsigned a3,
                                         unsigned b0, unsigned b1) {
    asm volatile(
        "mma.sync.aligned.m16n8k16.row.col.f32.bf16.bf16.f32 "
        "{%0,%1,%2,%3}, {%4,%5,%6,%7}, {%8,%9}, {%0,%1,%2,%3};"
        : "+f"(c[0]), "+f"(c[1]), "+f"(c[2]), "+f"(c[3])
        : "r"(a0), "r"(a1), "r"(a2), "r"(a3), "r"(b0), "r"(b1));
}

__device__ __forceinline__ float silu(float v) {
    return v / (1.0f + __expf(-1.702f * v));
}

#define XS 104    // bf16 smem row stride (qkv tiles)
#define FS 72     // bf16 smem row stride (final tiles, K=64)

// =============== Kernel 0: weight conversions only (14 blocks) ================
__global__ void __launch_bounds__(256) k_pre(const float* __restrict__ W,
                                             const float* __restrict__ Wf) {
    const int blk = blockIdx.x, tid = threadIdx.x;
    if (blk < 13) {
        const int o0 = blk * 16;
#pragma unroll
        for (int j = 0; j < 6; j++) {
            int i = j*256 + tid;
            int o = o0 + i / 96, k = i % 96;
            g_wh[o*96 + k] = __float2bfloat16_rn(W[rowmap_all(o)*97 + k]);
        }
    } else {
        for (int i = tid; i < 96*64; i += 256) {
            int o = i / 64, k = i - o*64;
            g_wf[i] = __float2bfloat16_rn(Wf[o*97 + 32 + k]);
        }
        if (tid < 208) g_bias[tid] = W[rowmap_all(tid)*97 + 96];
    }
}

// =============== Kernel A: GEMMs + prep (459 blocks, 256 thr) =================
__global__ void __launch_bounds__(256, 4) k_gemms(const float* __restrict__ x,
                                                  const int* __restrict__ coo0,
                                                  const int* __restrict__ coo1,
                                                  const int* __restrict__ a2a) {
    extern __shared__ __align__(16) float sm[];
    const int blk = blockIdx.x;
    const int tid = threadIdx.x;

    if (blk < 256) {
        __nv_bfloat16* sX  = (__nv_bfloat16*)sm;     // [64][XS]
        __nv_bfloat16* sWh = sX + 64*XS;             // [128][XS]
        float*         sB  = (float*)(sWh + 128*XS); // [128]
        const int t0 = blk * 64;

        for (int idx = tid; idx < 64*48; idx += 256) {
            int row = idx / 48, c = idx - row*48;
            float2 v = *(const float2*)&x[(t0 + row)*96 + 2*c];
            *(__nv_bfloat162*)&sX[row*XS + 2*c] = __float22bfloat162_rn(v);
        }
        for (int idx = tid; idx < 1536; idx += 256) {
            int row = idx / 12, q = idx - row*12;
            *(uint4*)&sWh[row*XS + q*8] =
                *(const uint4*)&g_wh[row*96 + q*8];
        }
        if (tid < 128) sB[tid] = g_bias[tid];
        __syncthreads();

        const int warp = tid >> 5, lane = tid & 31;
        const int mw = (warp & 3) * 16;
        const int nw = (warp >> 2) * 64;
        const int gr = lane >> 2;
        const int qp = (lane & 3) * 2;

        float acc[8][4];
#pragma unroll
        for (int n = 0; n < 8; n++)
#pragma unroll
            for (int j = 0; j < 4; j++) acc[n][j] = 0.f;

        const __nv_bfloat16* ab = &sX[(mw + gr)*XS + qp];
#pragma unroll
        for (int ks = 0; ks < 6; ks++) {
            const int k0 = ks * 16;
            unsigned a0 = *(const unsigned*)(ab + k0);
            unsigned a1 = *(const unsigned*)(ab + k0 + 8*XS);
            unsigned a2 = *(const unsigned*)(ab + k0 + 8);
            unsigned a3 = *(const unsigned*)(ab + k0 + 8*XS + 8);
#pragma unroll
            for (int n = 0; n < 8; n++) {
                const __nv_bfloat16* bb = &sWh[(nw + n*8 + gr)*XS + k0 + qp];
                unsigned b0 = *(const unsigned*)bb;
                unsigned b1 = *(const unsigned*)(bb + 8);
                mma16816(acc[n], a0, a1, a2, a3, b0, b1);
            }
        }
        const int r0 = t0 + mw + gr;       // global token (rows r0, r0+8)
        const int b0 = r0 >> 9;            // batch (same for r0+8: tile-aligned)
        const int tin = r0 & 511;          // token within batch
#pragma unroll
        for (int n = 0; n < 8; n++) {
            int col = nw + n*8 + qp;
            float bb0 = sB[col], bb1 = sB[col + 1];
            float2 v0 = make_float2(acc[n][0] + bb0, acc[n][1] + bb1);
            float2 v1 = make_float2(acc[n][2] + bb0, acc[n][3] + bb1);
            if (col < 40) {                // q channels -> g_y fp32
                *(float2*)&g_y[r0*YW + col]       = v0;
                *(float2*)&g_y[(r0 + 8)*YW + col] = v1;
            } else {                       // K/V -> g_kvh fp16 tile layout
                int cc = col - 40;
                int p   = cc / 40;
                int rem = cc - p*40;
                int i   = rem / 20;
                int hp  = (rem - i*20) / 10;
                int c   = rem % 10;
                int base = ((b0*2 + i)*4 + p*2 + hp)*SPLH + c;
                *(__half2*)&g_kvh[base + tin*12] =
                    __float22half2_rn(v0);
                *(__half2*)&g_kvh[base + (tin + 8)*12] =
                    __float22half2_rn(v1);
            }
        }
    } else if (blk < 331) {
        const int d = blk - 256;                     // 0..74
        __nv_bfloat16* sX  = (__nv_bfloat16*)sm;     // [64][XS]
        __nv_bfloat16* sWh = sX + 64*XS;             // [80][XS]
        float*         sB  = (float*)(sWh + 80*XS);  // [80]
        int*           sRow = (int*)(sB + 80);       // [64]
        const int r0 = d * 64;

        if (tid < 64) {
            int r = r0 + tid;
            int b = r / A2LEN, dd = r - b*A2LEN;
            sRow[tid] = b*NTOK + a2a[dd];
        }
        __syncthreads();
        for (int idx = tid; idx < 64*48; idx += 256) {
            int row = idx / 48, c = idx - row*48;
            float2 v = *(const float2*)&x[sRow[row]*96 + 2*c];
            *(__nv_bfloat162*)&sX[row*XS + 2*c] = __float22bfloat162_rn(v);
        }
        for (int idx = tid; idx < 960; idx += 256) {
            int row = idx / 12, q = idx - row*12;
            *(uint4*)&sWh[row*XS + q*8] =
                *(const uint4*)&g_wh[(128 + row)*96 + q*8];
        }
        if (tid < 80) sB[tid] = g_bias[128 + tid];
        __syncthreads();

        const int warp = tid >> 5, lane = tid & 31;
        const int mw = (warp & 3) * 16;
        const int nw = (warp >> 2) * 40;
        const int gr = lane >> 2;
        const int qp = (lane & 3) * 2;

        float acc[5][4];
#pragma unroll
        for (int n = 0; n < 5; n++)
#pragma unroll
            for (int j = 0; j < 4; j++) acc[n][j] = 0.f;

        const __nv_bfloat16* ab = &sX[(mw + gr)*XS + qp];
#pragma unroll
        for (int ks = 0; ks < 6; ks++) {
            const int k0 = ks * 16;
            unsigned a0 = *(const unsigned*)(ab + k0);
            unsigned a1 = *(const unsigned*)(ab + k0 + 8*XS);
            unsigned a2 = *(const unsigned*)(ab + k0 + 8);
            unsigned a3 = *(const unsigned*)(ab + k0 + 8*XS + 8);
#pragma unroll
            for (int n = 0; n < 5; n++) {
                const __nv_bfloat16* bb = &sWh[(nw + n*8 + gr)*XS + k0 + qp];
                unsigned b0 = *(const unsigned*)bb;
                unsigned b1 = *(const unsigned*)(bb + 8);
                mma16816(acc[n], a0, a1, a2, a3, b0, b1);
            }
        }
        const int rr = r0 + mw + gr;
#pragma unroll
        for (int n = 0; n < 5; n++) {
            int col = nw + n*8 + qp;
            if (col < 72) {
                int p = col / 24, c = col - p*24;
                float bb0 = sB[col], bb1 = sB[col + 1];
                *(float2*)&g_yd[p*(NDR*24) + rr*24 + c] =
                    make_float2(acc[n][0] + bb0, acc[n][1] + bb1);
                *(float2*)&g_yd[p*(NDR*24) + (rr + 8)*24 + c] =
                    make_float2(acc[n][2] + bb0, acc[n][3] + bb1);
            }
        }
    } else if (blk < 395) {
        const int pb = blk - 331;                // 0..63 coo transpose
#pragma unroll
        for (int j = 0; j < 2; j++) {
            int g = pb*512 + j*256 + tid;
            int i = g >> 14;
            int e = g & 16383;
            const int* coo = i ? coo1 : coo0;
            int src = coo[e*3 + 1];
            int tok = e >> 5, r = e & 31;
            g_src[i*16384 + r*512 + tok] = src;
        }
    } else {
        const int zb = blk - 395;                // 0..63 zero g_yb
        uint4 z = make_uint4(0,0,0,0);
#pragma unroll
        for (int j = 0; j < 8; j++)
            *(uint4*)&g_yb[(zb*2048 + j*256 + tid)*8] = z;
    }
}

// =============== Kernel B: attentions + SiLU -> g_yb (352 blocks, 256 thr) ====
__global__ void __launch_bounds__(256) k_attn(const int* __restrict__ a2a) {
    extern __shared__ __align__(16) float smf[];
    const int blk = blockIdx.x;
    const int tid = threadIdx.x;

    if (blk < 256) {
        __half* hs = (__half*)smf;               // 48 KB: [p*2+hp][tok][12]
        const int b    = blk >> 3;
        const int i    = (blk >> 2) & 1;
        const int quar = blk & 3;

        {   // fill: straight uint4 copy from g_kvh (layout identical)
            const uint4* src = (const uint4*)&g_kvh[(b*2 + i)*4*SPLH];
            uint4* dst = (uint4*)hs;
#pragma unroll
            for (int j = 0; j < 12; j++)
                dst[j*256 + tid] = src[j*256 + tid];
        }
        __syncthreads();

        const int t  = quar*128 + (tid >> 1);
        const int hp = tid & 1;
        const __half* sK = hs + hp*SPLH;
        const __half* sV = hs + (2 + hp)*SPLH;
        const float* qp = &g_y[(b*NTOK + t)*YW + i*20 + hp*10];
        __half2 qh[5];
#pragma unroll
        for (int w = 0; w < 5; w++)
            qh[w] = __floats2half2_rn(qp[2*w], qp[2*w+1]);
        const int* srcp = &g_src[i*16384 + t];
        const float scale = 0.44721359549995793f;   // 1/sqrt(5)
        float l0 = 0.f, l1 = 0.f;
        __half2 acc0 = __float2half2_rn(0.f), acc1 = acc0, acc2 = acc0,
                acc3 = acc0, acc4 = acc0;
#pragma unroll 4
        for (int r = 0; r < 32; r++) {
            int base = srcp[r*512] * 12;
            uint2 ka = *(const uint2*)&sK[base];
            uint2 kb = *(const uint2*)&sK[base + 4];
            unsigned int kc = *(const unsigned int*)&sK[base + 8];
            __half2 d0 = __habs2(__hsub2(qh[0], *(const __half2*)&ka.x));
            __half2 d1 = __habs2(__hsub2(qh[1], *(const __half2*)&ka.y));
            __half2 d2 = __habs2(__hsub2(qh[2], *(const __half2*)&kb.x));
            __half2 d3 = __habs2(__hsub2(qh[3], *(const __half2*)&kb.y));
            __half2 d4 = __habs2(__hsub2(qh[4], *(const __half2*)&kc));
            __half2 u = __hadd2(d0, d1);
            __half2 v = __hadd2(d3, d4);
            __half2 uv = __hadd2(__halves2half2(__low2half(u),  __low2half(v)),
                                 __halves2half2(__high2half(u), __high2half(v)));
            __half2 s2 = __hadd2(uv, d2);
            float2 sf = __half22float2(s2);
            float p0 = __expf(-sf.x * scale);
            float p1 = __expf(-sf.y * scale);
            l0 += p0; l1 += p1;
            __half h0 = __float2half_rn(p0), h1 = __float2half_rn(p1);
            __half2 pp00 = __halves2half2(h0, h0);
            __half2 pp01 = __halves2half2(h0, h1);
            __half2 pp11 = __halves2half2(h1, h1);
            uint2 va = *(const uint2*)&sV[base];
            uint2 vb = *(const uint2*)&sV[base + 4];
            unsigned int vc = *(const unsigned int*)&sV[base + 8];
            acc0 = __hfma2(pp00, *(const __half2*)&va.x, acc0);
            acc1 = __hfma2(pp00, *(const __half2*)&va.y, acc1);
            acc2 = __hfma2(pp01, *(const __half2*)&vb.x, acc2);
            acc3 = __hfma2(pp11, *(const __half2*)&vb.y, acc3);
            acc4 = __hfma2(pp11, *(const __half2*)&vc,   acc4);
        }
        float inv0 = 1.0f / l0, inv1 = 1.0f / l1;
        float2 f0 = __half22float2(acc0);
        float2 f1 = __half22float2(acc1);
        float2 f2 = __half22float2(acc2);
        float2 f3 = __half22float2(acc3);
        float2 f4 = __half22float2(acc4);
        float o_[10] = { f0.x*inv0, f0.y*inv0, f1.x*inv0, f1.y*inv0,
                         f2.x*inv0, f2.y*inv1, f3.x*inv1, f3.y*inv1,
                         f4.x*inv1, f4.y*inv1 };
        __nv_bfloat16* op = &g_yb[(b*NTOK + t)*64 + i*20 + hp*10];
#pragma unroll
        for (int w = 0; w < 5; w++)
            *(__nv_bfloat162*)&op[2*w] =
                __float22bfloat162_rn(make_float2(silu(o_[2*w]), silu(o_[2*w+1])));
    } else {
        const int idx = blk - 256;
        const int b     = idx & 31;
        const int d0    = (idx >> 5) * 64;       // 0,64,128
        float* sK = smf;
        float* sV = smf + A2LEN*24;
        const int P = NDR * 24;
        for (int j = tid; j < A2LEN*24; j += 256) {
            sK[j] = g_yd[P   + b*A2LEN*24 + j];
            sV[j] = g_yd[2*P + b*A2LEN*24 + j];
        }
        __syncthreads();
        const int dl = tid >> 2, h = tid & 3;
        const int d = d0 + dl;
        if (d >= A2LEN) return;
        const float* qp = &g_yd[(b*A2LEN + d)*24 + h*6];
        float q[6];
#pragma unroll
        for (int w = 0; w < 6; w++) q[w] = qp[w];
        const float scale = 0.4082482904638631f;    // 1/sqrt(6)
        float l = 0.f;
        float acc[6] = {0.f,0.f,0.f,0.f,0.f,0.f};
#pragma unroll 2
        for (int s = 0; s < A2LEN; s++) {
            const float* kp = &sK[s*24 + h*6];
            float2 ka = *(const float2*)kp;
            float2 kb = *(const float2*)(kp + 2);
            float2 kc = *(const float2*)(kp + 4);
            float ds = fabsf(q[0]-ka.x) + fabsf(q[1]-ka.y) + fabsf(q[2]-kb.x)
                     + fabsf(q[3]-kb.y) + fabsf(q[4]-kc.x) + fabsf(q[5]-kc.y);
            float p = __expf(-ds * scale);
            l += p;
            const float* vp = &sV[s*24 + h*6];
            float2 va = *(const float2*)vp;
            float2 vb = *(const float2*)(vp + 2);
            float2 vc = *(const float2*)(vp + 4);
            acc[0] += p*va.x; acc[1] += p*va.y; acc[2] += p*vb.x;
            acc[3] += p*vb.y; acc[4] += p*vc.x; acc[5] += p*vc.y;
        }
        {
            float ds = fabsf(q[0]) + fabsf(q[1]) + fabsf(q[2])
                     + fabsf(q[3]) + fabsf(q[4]) + fabsf(q[5]);
            l += __expf(-ds * scale);
        }
        float inv = 1.0f / l;
        int row = b*NTOK + a2a[d];
        __nv_bfloat16* op = &g_yb[row*64 + 40 + h*6];
#pragma unroll
        for (int w = 0; w < 3; w++)
            *(__nv_bfloat162*)&op[2*w] =
                __float22bfloat162_rn(make_float2(silu(acc[2*w]*inv),
                                                  silu(acc[2*w+1]*inv)));
    }
}

// =============== Kernel C: out = x + yb @ Wf^T + bias (bf16 MMA, 512 blks) ====
__global__ void __launch_bounds__(256) k_final(const float* __restrict__ x,
                                               const float* __restrict__ Wf,
                                               float* __restrict__ out) {
    __shared__ __align__(16) __nv_bfloat16 sY [32*FS];
    __shared__ __align__(16) __nv_bfloat16 sWf[96*FS];
    __shared__ __align__(16) float sB[96];
    const int t0 = blockIdx.x * 32;
    const int tid = threadIdx.x;

    {
        int t = tid >> 3, q = tid & 7;
        *(uint4*)&sY[t*FS + q*8] = *(const uint4*)&g_yb[(t0 + t)*64 + q*8];
    }
    for (int idx = tid; idx < 768; idx += 256) {
        int o = idx / 8, q = idx - o*8;
        *(uint4*)&sWf[o*FS + q*8] = *(const uint4*)&g_wf[o*64 + q*8];
    }
    if (tid < 96) sB[tid] = Wf[tid*97 + 96];
    __syncthreads();

    const int warp = tid >> 5, lane = tid & 31;
    const int mw = (warp & 1) * 16;
    const int nw = (warp >> 1) * 24;
    const int gr = lane >> 2;
    const int qp = (lane & 3) * 2;

    float acc[3][4];
#pragma unroll
    for (int n = 0; n < 3; n++)
#pragma unroll
        for (int j = 0; j < 4; j++) acc[n][j] = 0.f;

    const __nv_bfloat16* ab = &sY[(mw + gr)*FS + qp];
#pragma unroll
    for (int ks = 0; ks < 4; ks++) {
        const int k0 = ks * 16;
        unsigned a0 = *(const unsigned*)(ab + k0);
        unsigned a1 = *(const unsigned*)(ab + k0 + 8*FS);
        unsigned a2 = *(const unsigned*)(ab + k0 + 8);
        unsigned a3 = *(const unsigned*)(ab + k0 + 8*FS + 8);
#pragma unroll
        for (int n = 0; n < 3; n++) {
            const __nv_bfloat16* bb = &sWf[(nw + n*8 + gr)*FS + k0 + qp];
            unsigned b0 = *(const unsigned*)bb;
            unsigned b1 = *(const unsigned*)(bb + 8);
            mma16816(acc[n], a0, a1, a2, a3, b0, b1);
        }
    }
    const int r0 = t0 + mw + gr;
#pragma unroll
    for (int n = 0; n < 3; n++) {
        int col = nw + n*8 + qp;
        float bb0 = sB[col], bb1 = sB[col + 1];
        float2 x0 = *(const float2*)&x[r0*96 + col];
        float2 x1 = *(const float2*)&x[(r0 + 8)*96 + col];
        *(float2*)&out[r0*96 + col] =
            make_float2(acc[n][0] + bb0 + x0.x, acc[n][1] + bb1 + x0.y);
        *(float2*)&out[(r0 + 8)*96 + col] =
            make_float2(acc[n][2] + bb0 + x1.x, acc[n][3] + bb1 + x1.y);
    }
}

// ---------------- launch -------------------------------------------------------
extern "C" void kernel_launch(void* const* d_in, const int* in_sizes, int n_in,
                              void* d_out, int out_size) {
    const float* x    = (const float*)d_in[0];
    const float* wqv  = (const float*)d_in[1];
    const float* wf   = (const float*)d_in[2];
    const int*   coo0 = (const int*)d_in[3];
    const int*   coo1 = (const int*)d_in[4];
    const int*   a2a  = (const int*)d_in[5];
    float*       out  = (float*)d_out;
    (void)in_sizes; (void)n_in; (void)out_size;

    const int smemA = (64*XS + 128*XS) * 2 + 128 * 4;        // 40448
    const int smemB = 4 * SPLH * sizeof(__half);             // 49152
    static int inited = 0;
    if (!inited) {
        cudaFuncSetAttribute(k_gemms, cudaFuncAttributeMaxDynamicSharedMemorySize, smemA);
        cudaFuncSetAttribute(k_attn,  cudaFuncAttributeMaxDynamicSharedMemorySize, smemB);
        inited = 1;
    }

    k_pre  <<<14, 256>>>(wqv, wf);
    k_gemms<<<459, 256, smemA>>>(x, coo0, coo1, a2a);
    k_attn <<<352, 256, smemB>>>(a2a);
    k_final<<<512, 256>>>(x, wf, out);
}

// round 16
// speedup vs baseline: 1.2625x; 1.0007x over previous
#include <cuda_runtime.h>
#include <cuda_fp16.h>
#include <cuda_bf16.h>

#define BS    32
#define NTOK  512
#define A2LEN 150
#define NTOT  (BS*NTOK)          // 16384
#define NDR   (BS*A2LEN)         // 4800 = 75*64
#define YW    40                 // g_y holds q channels only
#define SPLH (NTOK*12)           // halves per (plane,hp) tile = 6144

// ---------------- scratch ----------------------------------------------------
__device__ float g_y  [NTOT * YW];        // q compact channels (fp32)
__device__ __half g_kvh[64 * 4 * SPLH];   // K/V fp16: [(b,i)][p*2+hp][tok][12]
__device__ float g_yd [3 * NDR * 24];
__device__ __nv_bfloat16 g_yb[NTOT * 64]; // SiLU(b) channels 32..96, bf16
__device__ unsigned short g_src16[2 * NTOK * 32]; // [i][r][t], value = src*12
__device__ __nv_bfloat16 g_wh[208 * 96];  // bf16 Wqv rows
__device__ __nv_bfloat16 g_wf[96 * 64];   // bf16 fanout W (cols 32..96)
__device__ float g_bias[208];

__device__ __forceinline__ int rowmap(int o) {
    if (o < 40)  return 32 + o;
    if (o < 80)  return 88 + o;
    if (o < 120) return 144 + o;
    return 32;
}
__device__ __forceinline__ int rowmap_all(int o) {
    if (o < 128) return rowmap(o);
    int oo = o - 128; if (oo > 71) oo = 71;
    int p = oo / 24, c = oo - p*24;
    return 96*p + 72 + c;
}

__device__ __forceinline__ void mma16816(float* c,
                                         unsigned a0, unsigned a1,
                                         unsigned a2, unsigned a3,
                                         unsigned b0, unsigned b1) {
    asm volatile(
        "mma.sync.aligned.m16n8k16.row.col.f32.bf16.bf16.f32 "
        "{%0,%1,%2,%3}, {%4,%5,%6,%7}, {%8,%9}, {%0,%1,%2,%3};"
        : "+f"(c[0]), "+f"(c[1]), "+f"(c[2]), "+f"(c[3])
        : "r"(a0), "r"(a1), "r"(a2), "r"(a3), "r"(b0), "r"(b1));
}

__device__ __forceinline__ float silu(float v) {
    return v / (1.0f + __expf(-1.702f * v));
}

#define XS 104
#define FS 72

// =============== Kernel 0: weight conversions only (14 blocks) ================
__global__ void __launch_bounds__(256) k_pre(const float* __restrict__ W,
                                             const float* __restrict__ Wf) {
    const int blk = blockIdx.x, tid = threadIdx.x;
    if (blk < 13) {
        const int o0 = blk * 16;
#pragma unroll
        for (int j = 0; j < 6; j++) {
            int i = j*256 + tid;
            int o = o0 + i / 96, k = i % 96;
            g_wh[o*96 + k] = __float2bfloat16_rn(W[rowmap_all(o)*97 + k]);
        }
    } else {
        for (int i = tid; i < 96*64; i += 256) {
            int o = i / 64, k = i - o*64;
            g_wf[i] = __float2bfloat16_rn(Wf[o*97 + 32 + k]);
        }
        if (tid < 208) g_bias[tid] = W[rowmap_all(tid)*97 + 96];
    }
}

// =============== Kernel A: GEMMs + prep (459 blocks, 256 thr) =================
__global__ void __launch_bounds__(256, 4) k_gemms(const float* __restrict__ x,
                                                  const int* __restrict__ coo0,
                                                  const int* __restrict__ coo1,
                                                  const int* __restrict__ a2a) {
    extern __shared__ __align__(16) float sm[];
    const int blk = blockIdx.x;
    const int tid = threadIdx.x;

    if (blk < 256) {
        __nv_bfloat16* sX  = (__nv_bfloat16*)sm;     // [64][XS]
        __nv_bfloat16* sWh = sX + 64*XS;             // [128][XS]
        float*         sB  = (float*)(sWh + 128*XS); // [128]
        const int t0 = blk * 64;

        for (int idx = tid; idx < 64*48; idx += 256) {
            int row = idx / 48, c = idx - row*48;
            float2 v = *(const float2*)&x[(t0 + row)*96 + 2*c];
            *(__nv_bfloat162*)&sX[row*XS + 2*c] = __float22bfloat162_rn(v);
        }
        for (int idx = tid; idx < 1536; idx += 256) {
            int row = idx / 12, q = idx - row*12;
            *(uint4*)&sWh[row*XS + q*8] =
                *(const uint4*)&g_wh[row*96 + q*8];
        }
        if (tid < 128) sB[tid] = g_bias[tid];
        __syncthreads();

        const int warp = tid >> 5, lane = tid & 31;
        const int mw = (warp & 3) * 16;
        const int nw = (warp >> 2) * 64;
        const int gr = lane >> 2;
        const int qp = (lane & 3) * 2;

        float acc[8][4];
#pragma unroll
        for (int n = 0; n < 8; n++)
#pragma unroll
            for (int j = 0; j < 4; j++) acc[n][j] = 0.f;

        const __nv_bfloat16* ab = &sX[(mw + gr)*XS + qp];
#pragma unroll
        for (int ks = 0; ks < 6; ks++) {
            const int k0 = ks * 16;
            unsigned a0 = *(const unsigned*)(ab + k0);
            unsigned a1 = *(const unsigned*)(ab + k0 + 8*XS);
            unsigned a2 = *(const unsigned*)(ab + k0 + 8);
            unsigned a3 = *(const unsigned*)(ab + k0 + 8*XS + 8);
#pragma unroll
            for (int n = 0; n < 8; n++) {
                const __nv_bfloat16* bb = &sWh[(nw + n*8 + gr)*XS + k0 + qp];
                unsigned b0 = *(const unsigned*)bb;
                unsigned b1 = *(const unsigned*)(bb + 8);
                mma16816(acc[n], a0, a1, a2, a3, b0, b1);
            }
        }
        const int r0 = t0 + mw + gr;
        const int b0 = r0 >> 9;
        const int tin = r0 & 511;
#pragma unroll
        for (int n = 0; n < 8; n++) {
            int col = nw + n*8 + qp;
            float bb0 = sB[col], bb1 = sB[col + 1];
            float2 v0 = make_float2(acc[n][0] + bb0, acc[n][1] + bb1);
            float2 v1 = make_float2(acc[n][2] + bb0, acc[n][3] + bb1);
            if (col < 40) {
                *(float2*)&g_y[r0*YW + col]       = v0;
                *(float2*)&g_y[(r0 + 8)*YW + col] = v1;
            } else {
                int cc = col - 40;
                int p   = cc / 40;
                int rem = cc - p*40;
                int i   = rem / 20;
                int hp  = (rem - i*20) / 10;
                int c   = rem % 10;
                int base = ((b0*2 + i)*4 + p*2 + hp)*SPLH + c;
                *(__half2*)&g_kvh[base + tin*12]       = __float22half2_rn(v0);
                *(__half2*)&g_kvh[base + (tin + 8)*12] = __float22half2_rn(v1);
            }
        }
    } else if (blk < 331) {
        const int d = blk - 256;
        __nv_bfloat16* sX  = (__nv_bfloat16*)sm;     // [64][XS]
        __nv_bfloat16* sWh = sX + 64*XS;             // [80][XS]
        float*         sB  = (float*)(sWh + 80*XS);  // [80]
        int*           sRow = (int*)(sB + 80);       // [64]
        const int r0 = d * 64;

        if (tid < 64) {
            int r = r0 + tid;
            int b = r / A2LEN, dd = r - b*A2LEN;
            sRow[tid] = b*NTOK + a2a[dd];
        }
        __syncthreads();
        for (int idx = tid; idx < 64*48; idx += 256) {
            int row = idx / 48, c = idx - row*48;
            float2 v = *(const float2*)&x[sRow[row]*96 + 2*c];
            *(__nv_bfloat162*)&sX[row*XS + 2*c] = __float22bfloat162_rn(v);
        }
        for (int idx = tid; idx < 960; idx += 256) {
            int row = idx / 12, q = idx - row*12;
            *(uint4*)&sWh[row*XS + q*8] =
                *(const uint4*)&g_wh[(128 + row)*96 + q*8];
        }
        if (tid < 80) sB[tid] = g_bias[128 + tid];
        __syncthreads();

        const int warp = tid >> 5, lane = tid & 31;
        const int mw = (warp & 3) * 16;
        const int nw = (warp >> 2) * 40;
        const int gr = lane >> 2;
        const int qp = (lane & 3) * 2;

        float acc[5][4];
#pragma unroll
        for (int n = 0; n < 5; n++)
#pragma unroll
            for (int j = 0; j < 4; j++) acc[n][j] = 0.f;

        const __nv_bfloat16* ab = &sX[(mw + gr)*XS + qp];
#pragma unroll
        for (int ks = 0; ks < 6; ks++) {
            const int k0 = ks * 16;
            unsigned a0 = *(const unsigned*)(ab + k0);
            unsigned a1 = *(const unsigned*)(ab + k0 + 8*XS);
            unsigned a2 = *(const unsigned*)(ab + k0 + 8);
            unsigned a3 = *(const unsigned*)(ab + k0 + 8*XS + 8);
#pragma unroll
            for (int n = 0; n < 5; n++) {
                const __nv_bfloat16* bb = &sWh[(nw + n*8 + gr)*XS + k0 + qp];
                unsigned b0 = *(const unsigned*)bb;
                unsigned b1 = *(const unsigned*)(bb + 8);
                mma16816(acc[n], a0, a1, a2, a3, b0, b1);
            }
        }
        const int rr = r0 + mw + gr;
#pragma unroll
        for (int n = 0; n < 5; n++) {
            int col = nw + n*8 + qp;
            if (col < 72) {
                int p = col / 24, c = col - p*24;
                float bb0 = sB[col], bb1 = sB[col + 1];
                *(float2*)&g_yd[p*(NDR*24) + rr*24 + c] =
                    make_float2(acc[n][0] + bb0, acc[n][1] + bb1);
                *(float2*)&g_yd[p*(NDR*24) + (rr + 8)*24 + c] =
                    make_float2(acc[n][2] + bb0, acc[n][3] + bb1);
            }
        }
    } else if (blk < 395) {
        const int pb = blk - 331;                // 0..63 coo transpose (u16, *12)
#pragma unroll
        for (int j = 0; j < 2; j++) {
            int g = pb*512 + j*256 + tid;
            int i = g >> 14;
            int e = g & 16383;
            const int* coo = i ? coo1 : coo0;
            int src = coo[e*3 + 1];
            int tok = e >> 5, r = e & 31;
            g_src16[i*16384 + r*512 + tok] = (unsigned short)(src * 12);
        }
    } else {
        const int zb = blk - 395;                // 0..63 zero g_yb
        uint4 z = make_uint4(0,0,0,0);
#pragma unroll
        for (int j = 0; j < 8; j++)
            *(uint4*)&g_yb[(zb*2048 + j*256 + tid)*8] = z;
    }
}

// =============== Kernel B: attentions + SiLU -> g_yb (352 blocks, 256 thr) ====
__global__ void __launch_bounds__(256) k_attn(const int* __restrict__ a2a) {
    extern __shared__ __align__(16) float smf[];
    const int blk = blockIdx.x;
    const int tid = threadIdx.x;

    if (blk < 256) {
        __half* hs = (__half*)smf;                        // 48 KB K/V
        unsigned short* sSrc = (unsigned short*)(hs + 4*SPLH); // 8 KB: [r][128]
        const int b    = blk >> 3;
        const int i    = (blk >> 2) & 1;
        const int quar = blk & 3;

        {   // K/V fill: straight uint4 copy from g_kvh
            const uint4* src = (const uint4*)&g_kvh[(b*2 + i)*4*SPLH];
            uint4* dst = (uint4*)hs;
#pragma unroll
            for (int j = 0; j < 12; j++)
                dst[j*256 + tid] = src[j*256 + tid];
        }
        {   // src fill: 32 r-rows x 128 tokens u16 = 512 uint4
            const int t0 = quar * 128;
#pragma unroll
            for (int j = 0; j < 2; j++) {
                int idx = j*256 + tid;               // 0..511
                int r = idx >> 4, q = idx & 15;      // 16 uint4 per row
                *(uint4*)&sSrc[r*128 + q*8] =
                    *(const uint4*)&g_src16[i*16384 + r*512 + t0 + q*8];
            }
        }
        __syncthreads();

        const int tt = tid >> 1;                     // token within quarter
        const int t  = quar*128 + tt;
        const int hp = tid & 1;
        const __half* sK = hs + hp*SPLH;
        const __half* sV = hs + (2 + hp)*SPLH;
        const float* qp = &g_y[(b*NTOK + t)*YW + i*20 + hp*10];
        __half2 qh[5];
#pragma unroll
        for (int w = 0; w < 5; w++)
            qh[w] = __floats2half2_rn(qp[2*w], qp[2*w+1]);
        const float scale = 0.44721359549995793f;   // 1/sqrt(5)
        float l0 = 0.f, l1 = 0.f;
        __half2 acc0 = __float2half2_rn(0.f), acc1 = acc0, acc2 = acc0,
                acc3 = acc0, acc4 = acc0;
#pragma unroll 4
        for (int r = 0; r < 32; r++) {
            int base = sSrc[r*128 + tt];             // LDS.U16 (pre-scaled *12)
            uint2 ka = *(const uint2*)&sK[base];
            uint2 kb = *(const uint2*)&sK[base + 4];
            unsigned int kc = *(const unsigned int*)&sK[base + 8];
            __half2 d0 = __habs2(__hsub2(qh[0], *(const __half2*)&ka.x));
            __half2 d1 = __habs2(__hsub2(qh[1], *(const __half2*)&ka.y));
            __half2 d2 = __habs2(__hsub2(qh[2], *(const __half2*)&kb.x));
            __half2 d3 = __habs2(__hsub2(qh[3], *(const __half2*)&kb.y));
            __half2 d4 = __habs2(__hsub2(qh[4], *(const __half2*)&kc));
            __half2 u = __hadd2(d0, d1);
            __half2 v = __hadd2(d3, d4);
            __half2 uv = __hadd2(__halves2half2(__low2half(u),  __low2half(v)),
                                 __halves2half2(__high2half(u), __high2half(v)));
            __half2 s2 = __hadd2(uv, d2);
            float2 sf = __half22float2(s2);
            float p0 = __expf(-sf.x * scale);
            float p1 = __expf(-sf.y * scale);
            l0 += p0; l1 += p1;
            __half h0 = __float2half_rn(p0), h1 = __float2half_rn(p1);
            __half2 pp00 = __halves2half2(h0, h0);
            __half2 pp01 = __halves2half2(h0, h1);
            __half2 pp11 = __halves2half2(h1, h1);
            uint2 va = *(const uint2*)&sV[base];
            uint2 vb = *(const uint2*)&sV[base + 4];
            unsigned int vc = *(const unsigned int*)&sV[base + 8];
            acc0 = __hfma2(pp00, *(const __half2*)&va.x, acc0);
            acc1 = __hfma2(pp00, *(const __half2*)&va.y, acc1);
            acc2 = __hfma2(pp01, *(const __half2*)&vb.x, acc2);
            acc3 = __hfma2(pp11, *(const __half2*)&vb.y, acc3);
            acc4 = __hfma2(pp11, *(const __half2*)&vc,   acc4);
        }
        float inv0 = 1.0f / l0, inv1 = 1.0f / l1;
        float2 f0 = __half22float2(acc0);
        float2 f1 = __half22float2(acc1);
        float2 f2 = __half22float2(acc2);
        float2 f3 = __half22float2(acc3);
        float2 f4 = __half22float2(acc4);
        float o_[10] = { f0.x*inv0, f0.y*inv0, f1.x*inv0, f1.y*inv0,
                         f2.x*inv0, f2.y*inv1, f3.x*inv1, f3.y*inv1,
                         f4.x*inv1, f4.y*inv1 };
        __nv_bfloat16* op = &g_yb[(b*NTOK + t)*64 + i*20 + hp*10];
#pragma unroll
        for (int w = 0; w < 5; w++)
            *(__nv_bfloat162*)&op[2*w] =
                __float22bfloat162_rn(make_float2(silu(o_[2*w]), silu(o_[2*w+1])));
    } else {
        const int idx = blk - 256;
        const int b     = idx & 31;
        const int d0    = (idx >> 5) * 64;
        float* sK = smf;
        float* sV = smf + A2LEN*24;
        const int P = NDR * 24;
        for (int j = tid; j < A2LEN*24; j += 256) {
            sK[j] = g_yd[P   + b*A2LEN*24 + j];
            sV[j] = g_yd[2*P + b*A2LEN*24 + j];
        }
        __syncthreads();
        const int dl = tid >> 2, h = tid & 3;
        const int d = d0 + dl;
        if (d >= A2LEN) return;
        const float* qp = &g_yd[(b*A2LEN + d)*24 + h*6];
        float q[6];
#pragma unroll
        for (int w = 0; w < 6; w++) q[w] = qp[w];
        const float scale = 0.4082482904638631f;    // 1/sqrt(6)
        float l = 0.f;
        float acc[6] = {0.f,0.f,0.f,0.f,0.f,0.f};
#pragma unroll 2
        for (int s = 0; s < A2LEN; s++) {
            const float* kp = &sK[s*24 + h*6];
            float2 ka = *(const float2*)kp;
            float2 kb = *(const float2*)(kp + 2);
            float2 kc = *(const float2*)(kp + 4);
            float ds = fabsf(q[0]-ka.x) + fabsf(q[1]-ka.y) + fabsf(q[2]-kb.x)
                     + fabsf(q[3]-kb.y) + fabsf(q[4]-kc.x) + fabsf(q[5]-kc.y);
            float p = __expf(-ds * scale);
            l += p;
            const float* vp = &sV[s*24 + h*6];
            float2 va = *(const float2*)vp;
            float2 vb = *(const float2*)(vp + 2);
            float2 vc = *(const float2*)(vp + 4);
            acc[0] += p*va.x; acc[1] += p*va.y; acc[2] += p*vb.x;
            acc[3] += p*vb.y; acc[4] += p*vc.x; acc[5] += p*vc.y;
        }
        {
            float ds = fabsf(q[0]) + fabsf(q[1]) + fabsf(q[2])
                     + fabsf(q[3]) + fabsf(q[4]) + fabsf(q[5]);
            l += __expf(-ds * scale);
        }
        float inv = 1.0f / l;
        int row = b*NTOK + a2a[d];
        __nv_bfloat16* op = &g_yb[row*64 + 40 + h*6];
#pragma unroll
        for (int w = 0; w < 3; w++)
            *(__nv_bfloat162*)&op[2*w] =
                __float22bfloat162_rn(make_float2(silu(acc[2*w]*inv),
                                                  silu(acc[2*w+1]*inv)));
    }
}

// =============== Kernel C: out = x + yb @ Wf^T + bias (bf16 MMA, 512 blks) ====
__global__ void __launch_bounds__(256) k_final(const float* __restrict__ x,
                                               const float* __restrict__ Wf,
                                               float* __restrict__ out) {
    __shared__ __align__(16) __nv_bfloat16 sY [32*FS];
    __shared__ __align__(16) __nv_bfloat16 sWf[96*FS];
    __shared__ __align__(16) float sB[96];
    const int t0 = blockIdx.x * 32;
    const int tid = threadIdx.x;

    {
        int t = tid >> 3, q = tid & 7;
        *(uint4*)&sY[t*FS + q*8] = *(const uint4*)&g_yb[(t0 + t)*64 + q*8];
    }
    for (int idx = tid; idx < 768; idx += 256) {
        int o = idx / 8, q = idx - o*8;
        *(uint4*)&sWf[o*FS + q*8] = *(const uint4*)&g_wf[o*64 + q*8];
    }
    if (tid < 96) sB[tid] = Wf[tid*97 + 96];
    __syncthreads();

    const int warp = tid >> 5, lane = tid & 31;
    const int mw = (warp & 1) * 16;
    const int nw = (warp >> 1) * 24;
    const int gr = lane >> 2;
    const int qp = (lane & 3) * 2;

    float acc[3][4];
#pragma unroll
    for (int n = 0; n < 3; n++)
#pragma unroll
        for (int j = 0; j < 4; j++) acc[n][j] = 0.f;

    const __nv_bfloat16* ab = &sY[(mw + gr)*FS + qp];
#pragma unroll
    for (int ks = 0; ks < 4; ks++) {
        const int k0 = ks * 16;
        unsigned a0 = *(const unsigned*)(ab + k0);
        unsigned a1 = *(const unsigned*)(ab + k0 + 8*FS);
        unsigned a2 = *(const unsigned*)(ab + k0 + 8);
        unsigned a3 = *(const unsigned*)(ab + k0 + 8*FS + 8);
#pragma unroll
        for (int n = 0; n < 3; n++) {
            const __nv_bfloat16* bb = &sWf[(nw + n*8 + gr)*FS + k0 + qp];
            unsigned b0 = *(const unsigned*)bb;
            unsigned b1 = *(const unsigned*)(bb + 8);
            mma16816(acc[n], a0, a1, a2, a3, b0, b1);
        }
    }
    const int r0 = t0 + mw + gr;
#pragma unroll
    for (int n = 0; n < 3; n++) {
        int col = nw + n*8 + qp;
        float bb0 = sB[col], bb1 = sB[col + 1];
        float2 x0 = *(const float2*)&x[r0*96 + col];
        float2 x1 = *(const float2*)&x[(r0 + 8)*96 + col];
        *(float2*)&out[r0*96 + col] =
            make_float2(acc[n][0] + bb0 + x0.x, acc[n][1] + bb1 + x0.y);
        *(float2*)&out[(r0 + 8)*96 + col] =
            make_float2(acc[n][2] + bb0 + x1.x, acc[n][3] + bb1 + x1.y);
    }
}

// ---------------- launch -------------------------------------------------------
extern "C" void kernel_launch(void* const* d_in, const int* in_sizes, int n_in,
                              void* d_out, int out_size) {
    const float* x    = (const float*)d_in[0];
    const float* wqv  = (const float*)d_in[1];
    const float* wf   = (const float*)d_in[2];
    const int*   coo0 = (const int*)d_in[3];
    const int*   coo1 = (const int*)d_in[4];
    const int*   a2a  = (const int*)d_in[5];
    float*       out  = (float*)d_out;
    (void)in_sizes; (void)n_in; (void)out_size;

    const int smemA = (64*XS + 128*XS) * 2 + 128 * 4;        // 40448
    const int smemB = 4 * SPLH * sizeof(__half) + 32*128*2;  // 49152 + 8192
    static int inited = 0;
    if (!inited) {
        cudaFuncSetAttribute(k_gemms, cudaFuncAttributeMaxDynamicSharedMemorySize, smemA);
        cudaFuncSetAttribute(k_attn,  cudaFuncAttributeMaxDynamicSharedMemorySize, smemB);
        inited = 1;
    }

    k_pre  <<<14, 256>>>(wqv, wf);
    k_gemms<<<459, 256, smemA>>>(x, coo0, coo1, a2a);
    k_attn <<<352, 256, smemB>>>(a2a);
    k_final<<<512, 256>>>(x, wf, out);
}

// round 17
// speedup vs baseline: 1.3395x; 1.0610x over previous
#include <cuda_runtime.h>
#include <cuda_fp16.h>
#include <cuda_bf16.h>

#define BS    32
#define NTOK  512
#define A2LEN 150
#define NTOT  (BS*NTOK)          // 16384
#define NDR   (BS*A2LEN)         // 4800 = 75*64
#define YW    40                 // g_y holds q channels only
#define SPLH (NTOK*12)           // halves per (plane,hp) tile = 6144

// ---------------- scratch ----------------------------------------------------
__device__ float g_y  [NTOT * YW];        // q compact channels (fp32)
__device__ __half g_kvh[64 * 4 * SPLH];   // K/V fp16: [(b,i)][p*2+hp][tok][12]
__device__ float g_yd [3 * NDR * 24];
__device__ __nv_bfloat16 g_yb[NTOT * 64]; // SiLU(b) channels 32..96, bf16
__device__ unsigned short g_src16[2 * NTOK * 32]; // [i][r][t], value = src*12
__device__ __nv_bfloat16 g_wh[208 * 96];  // bf16 Wqv rows
__device__ __nv_bfloat16 g_wf[96 * 64];   // bf16 fanout W (cols 32..96)
__device__ float g_bias[208];

__device__ __forceinline__ int rowmap(int o) {
    if (o < 40)  return 32 + o;
    if (o < 80)  return 88 + o;
    if (o < 120) return 144 + o;
    return 32;
}
__device__ __forceinline__ int rowmap_all(int o) {
    if (o < 128) return rowmap(o);
    int oo = o - 128; if (oo > 71) oo = 71;
    int p = oo / 24, c = oo - p*24;
    return 96*p + 72 + c;
}

__device__ __forceinline__ void mma16816(float* c,
                                         unsigned a0, unsigned a1,
                                         unsigned a2, unsigned a3,
                                         unsigned b0, unsigned b1) {
    asm volatile(
        "mma.sync.aligned.m16n8k16.row.col.f32.bf16.bf16.f32 "
        "{%0,%1,%2,%3}, {%4,%5,%6,%7}, {%8,%9}, {%0,%1,%2,%3};"
        : "+f"(c[0]), "+f"(c[1]), "+f"(c[2]), "+f"(c[3])
        : "r"(a0), "r"(a1), "r"(a2), "r"(a3), "r"(b0), "r"(b1));
}

__device__ __forceinline__ float silu(float v) {
    return v / (1.0f + __expf(-1.702f * v));
}

#define XS 104
#define FS 72

// =============== Kernel 0: weight conversions only (14 blocks) ================
__global__ void __launch_bounds__(256) k_pre(const float* __restrict__ W,
                                             const float* __restrict__ Wf) {
    const int blk = blockIdx.x, tid = threadIdx.x;
    if (blk < 13) {
        const int o0 = blk * 16;
#pragma unroll
        for (int j = 0; j < 6; j++) {
            int i = j*256 + tid;
            int o = o0 + i / 96, k = i % 96;
            g_wh[o*96 + k] = __float2bfloat16_rn(W[rowmap_all(o)*97 + k]);
        }
    } else {
        for (int i = tid; i < 96*64; i += 256) {
            int o = i / 64, k = i - o*64;
            g_wf[i] = __float2bfloat16_rn(Wf[o*97 + 32 + k]);
        }
        if (tid < 208) g_bias[tid] = W[rowmap_all(tid)*97 + 96];
    }
#if __CUDA_ARCH__ >= 900
    cudaTriggerProgrammaticLaunchCompletion();
#endif
}

// =============== Kernel A: GEMMs + prep (459 blocks, 256 thr) =================
__global__ void __launch_bounds__(256, 4) k_gemms(const float* __restrict__ x,
                                                  const int* __restrict__ coo0,
                                                  const int* __restrict__ coo1,
                                                  const int* __restrict__ a2a) {
    extern __shared__ __align__(16) float sm[];
    const int blk = blockIdx.x;
    const int tid = threadIdx.x;

    if (blk < 256) {
        __nv_bfloat16* sX  = (__nv_bfloat16*)sm;     // [64][XS]
        __nv_bfloat16* sWh = sX + 64*XS;             // [128][XS]
        float*         sB  = (float*)(sWh + 128*XS); // [128]
        const int t0 = blk * 64;

        for (int idx = tid; idx < 64*48; idx += 256) {   // X: input only
            int row = idx / 48, c = idx - row*48;
            float2 v = *(const float2*)&x[(t0 + row)*96 + 2*c];
            *(__nv_bfloat162*)&sX[row*XS + 2*c] = __float22bfloat162_rn(v);
        }
#if __CUDA_ARCH__ >= 900
        cudaGridDependencySynchronize();                 // wait for k_pre
#endif
        for (int idx = tid; idx < 1536; idx += 256) {
            int row = idx / 12, q = idx - row*12;
            *(uint4*)&sWh[row*XS + q*8] =
                *(const uint4*)&g_wh[row*96 + q*8];
        }
        if (tid < 128) sB[tid] = g_bias[tid];
        __syncthreads();

        const int warp = tid >> 5, lane = tid & 31;
        const int mw = (warp & 3) * 16;
        const int nw = (warp >> 2) * 64;
        const int gr = lane >> 2;
        const int qp = (lane & 3) * 2;

        float acc[8][4];
#pragma unroll
        for (int n = 0; n < 8; n++)
#pragma unroll
            for (int j = 0; j < 4; j++) acc[n][j] = 0.f;

        const __nv_bfloat16* ab = &sX[(mw + gr)*XS + qp];
#pragma unroll
        for (int ks = 0; ks < 6; ks++) {
            const int k0 = ks * 16;
            unsigned a0 = *(const unsigned*)(ab + k0);
            unsigned a1 = *(const unsigned*)(ab + k0 + 8*XS);
            unsigned a2 = *(const unsigned*)(ab + k0 + 8);
            unsigned a3 = *(const unsigned*)(ab + k0 + 8*XS + 8);
#pragma unroll
            for (int n = 0; n < 8; n++) {
                const __nv_bfloat16* bb = &sWh[(nw + n*8 + gr)*XS + k0 + qp];
                unsigned b0 = *(const unsigned*)bb;
                unsigned b1 = *(const unsigned*)(bb + 8);
                mma16816(acc[n], a0, a1, a2, a3, b0, b1);
            }
        }
        const int r0 = t0 + mw + gr;
        const int b0 = r0 >> 9;
        const int tin = r0 & 511;
#pragma unroll
        for (int n = 0; n < 8; n++) {
            int col = nw + n*8 + qp;
            float bb0 = sB[col], bb1 = sB[col + 1];
            float2 v0 = make_float2(acc[n][0] + bb0, acc[n][1] + bb1);
            float2 v1 = make_float2(acc[n][2] + bb0, acc[n][3] + bb1);
            if (col < 40) {
                *(float2*)&g_y[r0*YW + col]       = v0;
                *(float2*)&g_y[(r0 + 8)*YW + col] = v1;
            } else {
                int cc = col - 40;
                int p   = cc / 40;
                int rem = cc - p*40;
                int i   = rem / 20;
                int hp  = (rem - i*20) / 10;
                int c   = rem % 10;
                int base = ((b0*2 + i)*4 + p*2 + hp)*SPLH + c;
                *(__half2*)&g_kvh[base + tin*12]       = __float22half2_rn(v0);
                *(__half2*)&g_kvh[base + (tin + 8)*12] = __float22half2_rn(v1);
            }
        }
    } else if (blk < 331) {
        const int d = blk - 256;
        __nv_bfloat16* sX  = (__nv_bfloat16*)sm;     // [64][XS]
        __nv_bfloat16* sWh = sX + 64*XS;             // [80][XS]
        float*         sB  = (float*)(sWh + 80*XS);  // [80]
        int*           sRow = (int*)(sB + 80);       // [64]
        const int r0 = d * 64;

        if (tid < 64) {
            int r = r0 + tid;
            int b = r / A2LEN, dd = r - b*A2LEN;
            sRow[tid] = b*NTOK + a2a[dd];
        }
        __syncthreads();
        for (int idx = tid; idx < 64*48; idx += 256) {   // X: input only
            int row = idx / 48, c = idx - row*48;
            float2 v = *(const float2*)&x[sRow[row]*96 + 2*c];
            *(__nv_bfloat162*)&sX[row*XS + 2*c] = __float22bfloat162_rn(v);
        }
#if __CUDA_ARCH__ >= 900
        cudaGridDependencySynchronize();                 // wait for k_pre
#endif
        for (int idx = tid; idx < 960; idx += 256) {
            int row = idx / 12, q = idx - row*12;
            *(uint4*)&sWh[row*XS + q*8] =
                *(const uint4*)&g_wh[(128 + row)*96 + q*8];
        }
        if (tid < 80) sB[tid] = g_bias[128 + tid];
        __syncthreads();

        const int warp = tid >> 5, lane = tid & 31;
        const int mw = (warp & 3) * 16;
        const int nw = (warp >> 2) * 40;
        const int gr = lane >> 2;
        const int qp = (lane & 3) * 2;

        float acc[5][4];
#pragma unroll
        for (int n = 0; n < 5; n++)
#pragma unroll
            for (int j = 0; j < 4; j++) acc[n][j] = 0.f;

        const __nv_bfloat16* ab = &sX[(mw + gr)*XS + qp];
#pragma unroll
        for (int ks = 0; ks < 6; ks++) {
            const int k0 = ks * 16;
            unsigned a0 = *(const unsigned*)(ab + k0);
            unsigned a1 = *(const unsigned*)(ab + k0 + 8*XS);
            unsigned a2 = *(const unsigned*)(ab + k0 + 8);
            unsigned a3 = *(const unsigned*)(ab + k0 + 8*XS + 8);
#pragma unroll
            for (int n = 0; n < 5; n++) {
                const __nv_bfloat16* bb = &sWh[(nw + n*8 + gr)*XS + k0 + qp];
                unsigned b0 = *(const unsigned*)bb;
                unsigned b1 = *(const unsigned*)(bb + 8);
                mma16816(acc[n], a0, a1, a2, a3, b0, b1);
            }
        }
        const int rr = r0 + mw + gr;
#pragma unroll
        for (int n = 0; n < 5; n++) {
            int col = nw + n*8 + qp;
            if (col < 72) {
                int p = col / 24, c = col - p*24;
                float bb0 = sB[col], bb1 = sB[col + 1];
                *(float2*)&g_yd[p*(NDR*24) + rr*24 + c] =
                    make_float2(acc[n][0] + bb0, acc[n][1] + bb1);
                *(float2*)&g_yd[p*(NDR*24) + (rr + 8)*24 + c] =
                    make_float2(acc[n][2] + bb0, acc[n][3] + bb1);
            }
        }
    } else if (blk < 395) {
        const int pb = blk - 331;                // coo transpose: inputs only
#pragma unroll
        for (int j = 0; j < 2; j++) {
            int g = pb*512 + j*256 + tid;
            int i = g >> 14;
            int e = g & 16383;
            const int* coo = i ? coo1 : coo0;
            int src = coo[e*3 + 1];
            int tok = e >> 5, r = e & 31;
            g_src16[i*16384 + r*512 + tok] = (unsigned short)(src * 12);
        }
    } else {
        const int zb = blk - 395;                // zero g_yb
        uint4 z = make_uint4(0,0,0,0);
#pragma unroll
        for (int j = 0; j < 8; j++)
            *(uint4*)&g_yb[(zb*2048 + j*256 + tid)*8] = z;
    }
#if __CUDA_ARCH__ >= 900
    cudaTriggerProgrammaticLaunchCompletion();
#endif
}

// =============== Kernel B: attentions + SiLU -> g_yb (352 blocks, 256 thr) ====
__global__ void __launch_bounds__(256) k_attn(const int* __restrict__ a2a) {
    extern __shared__ __align__(16) float smf[];
    const int blk = blockIdx.x;
    const int tid = threadIdx.x;

#if __CUDA_ARCH__ >= 900
    cudaGridDependencySynchronize();                 // all fills depend on k_gemms
#endif
    if (blk < 256) {
        __half* hs = (__half*)smf;                        // 48 KB K/V
        unsigned short* sSrc = (unsigned short*)(hs + 4*SPLH); // 8 KB
        const int b    = blk >> 3;
        const int i    = (blk >> 2) & 1;
        const int quar = blk & 3;

        {
            const uint4* src = (const uint4*)&g_kvh[(b*2 + i)*4*SPLH];
            uint4* dst = (uint4*)hs;
#pragma unroll
            for (int j = 0; j < 12; j++)
                dst[j*256 + tid] = src[j*256 + tid];
        }
        {
            const int t0 = quar * 128;
#pragma unroll
            for (int j = 0; j < 2; j++) {
                int idx = j*256 + tid;
                int r = idx >> 4, q = idx & 15;
                *(uint4*)&sSrc[r*128 + q*8] =
                    *(const uint4*)&g_src16[i*16384 + r*512 + t0 + q*8];
            }
        }
        __syncthreads();

        const int tt = tid >> 1;
        const int t  = quar*128 + tt;
        const int hp = tid & 1;
        const __half* sK = hs + hp*SPLH;
        const __half* sV = hs + (2 + hp)*SPLH;
        const float* qp = &g_y[(b*NTOK + t)*YW + i*20 + hp*10];
        __half2 qh[5];
#pragma unroll
        for (int w = 0; w < 5; w++)
            qh[w] = __floats2half2_rn(qp[2*w], qp[2*w+1]);
        const float scale = 0.44721359549995793f;   // 1/sqrt(5)
        float l0 = 0.f, l1 = 0.f;
        __half2 acc0 = __float2half2_rn(0.f), acc1 = acc0, acc2 = acc0,
                acc3 = acc0, acc4 = acc0;
#pragma unroll 4
        for (int r = 0; r < 32; r++) {
            int base = sSrc[r*128 + tt];
            uint2 ka = *(const uint2*)&sK[base];
            uint2 kb = *(const uint2*)&sK[base + 4];
            unsigned int kc = *(const unsigned int*)&sK[base + 8];
            __half2 d0 = __habs2(__hsub2(qh[0], *(const __half2*)&ka.x));
            __half2 d1 = __habs2(__hsub2(qh[1], *(const __half2*)&ka.y));
            __half2 d2 = __habs2(__hsub2(qh[2], *(const __half2*)&kb.x));
            __half2 d3 = __habs2(__hsub2(qh[3], *(const __half2*)&kb.y));
            __half2 d4 = __habs2(__hsub2(qh[4], *(const __half2*)&kc));
            __half2 u = __hadd2(d0, d1);
            __half2 v = __hadd2(d3, d4);
            __half2 uv = __hadd2(__halves2half2(__low2half(u),  __low2half(v)),
                                 __halves2half2(__high2half(u), __high2half(v)));
            __half2 s2 = __hadd2(uv, d2);
            float2 sf = __half22float2(s2);
            float p0 = __expf(-sf.x * scale);
            float p1 = __expf(-sf.y * scale);
            l0 += p0; l1 += p1;
            __half h0 = __float2half_rn(p0), h1 = __float2half_rn(p1);
            __half2 pp00 = __halves2half2(h0, h0);
            __half2 pp01 = __halves2half2(h0, h1);
            __half2 pp11 = __halves2half2(h1, h1);
            uint2 va = *(const uint2*)&sV[base];
            uint2 vb = *(const uint2*)&sV[base + 4];
            unsigned int vc = *(const unsigned int*)&sV[base + 8];
            acc0 = __hfma2(pp00, *(const __half2*)&va.x, acc0);
            acc1 = __hfma2(pp00, *(const __half2*)&va.y, acc1);
            acc2 = __hfma2(pp01, *(const __half2*)&vb.x, acc2);
            acc3 = __hfma2(pp11, *(const __half2*)&vb.y, acc3);
            acc4 = __hfma2(pp11, *(const __half2*)&vc,   acc4);
        }
        float inv0 = 1.0f / l0, inv1 = 1.0f / l1;
        float2 f0 = __half22float2(acc0);
        float2 f1 = __half22float2(acc1);
        float2 f2 = __half22float2(acc2);
        float2 f3 = __half22float2(acc3);
        float2 f4 = __half22float2(acc4);
        float o_[10] = { f0.x*inv0, f0.y*inv0, f1.x*inv0, f1.y*inv0,
                         f2.x*inv0, f2.y*inv1, f3.x*inv1, f3.y*inv1,
                         f4.x*inv1, f4.y*inv1 };
        __nv_bfloat16* op = &g_yb[(b*NTOK + t)*64 + i*20 + hp*10];
#pragma unroll
        for (int w = 0; w < 5; w++)
            *(__nv_bfloat162*)&op[2*w] =
                __float22bfloat162_rn(make_float2(silu(o_[2*w]), silu(o_[2*w+1])));
    } else {
        const int idx = blk - 256;
        const int b     = idx & 31;
        const int d0    = (idx >> 5) * 64;
        float* sK = smf;
        float* sV = smf + A2LEN*24;
        const int P = NDR * 24;
        for (int j = tid; j < A2LEN*24; j += 256) {
            sK[j] = g_yd[P   + b*A2LEN*24 + j];
            sV[j] = g_yd[2*P + b*A2LEN*24 + j];
        }
        __syncthreads();
        const int dl = tid >> 2, h = tid & 3;
        const int d = d0 + dl;
        if (d >= A2LEN) return;
        const float* qp = &g_yd[(b*A2LEN + d)*24 + h*6];
        float q[6];
#pragma unroll
        for (int w = 0; w < 6; w++) q[w] = qp[w];
        const float scale = 0.4082482904638631f;    // 1/sqrt(6)
        float l = 0.f;
        float acc[6] = {0.f,0.f,0.f,0.f,0.f,0.f};
#pragma unroll 2
        for (int s = 0; s < A2LEN; s++) {
            const float* kp = &sK[s*24 + h*6];
            float2 ka = *(const float2*)kp;
            float2 kb = *(const float2*)(kp + 2);
            float2 kc = *(const float2*)(kp + 4);
            float ds = fabsf(q[0]-ka.x) + fabsf(q[1]-ka.y) + fabsf(q[2]-kb.x)
                     + fabsf(q[3]-kb.y) + fabsf(q[4]-kc.x) + fabsf(q[5]-kc.y);
            float p = __expf(-ds * scale);
            l += p;
            const float* vp = &sV[s*24 + h*6];
            float2 va = *(const float2*)vp;
            float2 vb = *(const float2*)(vp + 2);
            float2 vc = *(const float2*)(vp + 4);
            acc[0] += p*va.x; acc[1] += p*va.y; acc[2] += p*vb.x;
            acc[3] += p*vb.y; acc[4] += p*vc.x; acc[5] += p*vc.y;
        }
        {
            float ds = fabsf(q[0]) + fabsf(q[1]) + fabsf(q[2])
                     + fabsf(q[3]) + fabsf(q[4]) + fabsf(q[5]);
            l += __expf(-ds * scale);
        }
        float inv = 1.0f / l;
        int row = b*NTOK + a2a[d];
        __nv_bfloat16* op = &g_yb[row*64 + 40 + h*6];
#pragma unroll
        for (int w = 0; w < 3; w++)
            *(__nv_bfloat162*)&op[2*w] =
                __float22bfloat162_rn(make_float2(silu(acc[2*w]*inv),
                                                  silu(acc[2*w+1]*inv)));
    }
#if __CUDA_ARCH__ >= 900
    cudaTriggerProgrammaticLaunchCompletion();
#endif
}

// =============== Kernel C: out = x + yb @ Wf^T + bias (bf16 MMA, 512 blks) ====
__global__ void __launch_bounds__(256) k_final(const float* __restrict__ x,
                                               const float* __restrict__ Wf,
                                               float* __restrict__ out) {
    __shared__ __align__(16) __nv_bfloat16 sY [32*FS];
    __shared__ __align__(16) __nv_bfloat16 sWf[96*FS];
    __shared__ __align__(16) float sB[96];
    const int t0 = blockIdx.x * 32;
    const int tid = threadIdx.x;

    // dependency-free fills first (g_wf from k_pre, Wf input)
    for (int idx = tid; idx < 768; idx += 256) {
        int o = idx / 8, q = idx - o*8;
        *(uint4*)&sWf[o*FS + q*8] = *(const uint4*)&g_wf[o*64 + q*8];
    }
    if (tid < 96) sB[tid] = Wf[tid*97 + 96];
#if __CUDA_ARCH__ >= 900
    cudaGridDependencySynchronize();                 // wait for k_attn
#endif
    {
        int t = tid >> 3, q = tid & 7;
        *(uint4*)&sY[t*FS + q*8] = *(const uint4*)&g_yb[(t0 + t)*64 + q*8];
    }
    __syncthreads();

    const int warp = tid >> 5, lane = tid & 31;
    const int mw = (warp & 1) * 16;
    const int nw = (warp >> 1) * 24;
    const int gr = lane >> 2;
    const int qp = (lane & 3) * 2;

    float acc[3][4];
#pragma unroll
    for (int n = 0; n < 3; n++)
#pragma unroll
        for (int j = 0; j < 4; j++) acc[n][j] = 0.f;

    const __nv_bfloat16* ab = &sY[(mw + gr)*FS + qp];
#pragma unroll
    for (int ks = 0; ks < 4; ks++) {
        const int k0 = ks * 16;
        unsigned a0 = *(const unsigned*)(ab + k0);
        unsigned a1 = *(const unsigned*)(ab + k0 + 8*FS);
        unsigned a2 = *(const unsigned*)(ab + k0 + 8);
        unsigned a3 = *(const unsigned*)(ab + k0 + 8*FS + 8);
#pragma unroll
        for (int n = 0; n < 3; n++) {
            const __nv_bfloat16* bb = &sWf[(nw + n*8 + gr)*FS + k0 + qp];
            unsigned b0 = *(const unsigned*)bb;
            unsigned b1 = *(const unsigned*)(bb + 8);
            mma16816(acc[n], a0, a1, a2, a3, b0, b1);
        }
    }
    const int r0 = t0 + mw + gr;
#pragma unroll
    for (int n = 0; n < 3; n++) {
        int col = nw + n*8 + qp;
        float bb0 = sB[col], bb1 = sB[col + 1];
        float2 x0 = *(const float2*)&x[r0*96 + col];
        float2 x1 = *(const float2*)&x[(r0 + 8)*96 + col];
        *(float2*)&out[r0*96 + col] =
            make_float2(acc[n][0] + bb0 + x0.x, acc[n][1] + bb1 + x0.y);
        *(float2*)&out[(r0 + 8)*96 + col] =
            make_float2(acc[n][2] + bb0 + x1.x, acc[n][3] + bb1 + x1.y);
    }
}

// ---------------- launch -------------------------------------------------------
extern "C" void kernel_launch(void* const* d_in, const int* in_sizes, int n_in,
                              void* d_out, int out_size) {
    const float* x    = (const float*)d_in[0];
    const float* wqv  = (const float*)d_in[1];
    const float* wf   = (const float*)d_in[2];
    const int*   coo0 = (const int*)d_in[3];
    const int*   coo1 = (const int*)d_in[4];
    const int*   a2a  = (const int*)d_in[5];
    float*       out  = (float*)d_out;
    (void)in_sizes; (void)n_in; (void)out_size;

    const int smemA = (64*XS + 128*XS) * 2 + 128 * 4;        // 40448
    const int smemB = 4 * SPLH * sizeof(__half) + 32*128*2;  // 57344
    static int inited = 0;
    if (!inited) {
        cudaFuncSetAttribute(k_gemms, cudaFuncAttributeMaxDynamicSharedMemorySize, smemA);
        cudaFuncSetAttribute(k_attn,  cudaFuncAttributeMaxDynamicSharedMemorySize, smemB);
        inited = 1;
    }

    k_pre<<<14, 256>>>(wqv, wf);

    cudaLaunchAttribute attr[1];
    attr[0].id = cudaLaunchAttributeProgrammaticStreamSerialization;
    attr[0].val.programmaticStreamSerializationAllowed = 1;

    {   // k_gemms with PDL
        cudaLaunchConfig_t cfg = {};
        cfg.gridDim = dim3(459); cfg.blockDim = dim3(256);
        cfg.dynamicSmemBytes = smemA;
        cfg.attrs = attr; cfg.numAttrs = 1;
        cudaLaunchKernelEx(&cfg, k_gemms, x, coo0, coo1, a2a);
    }
    {   // k_attn with PDL
        cudaLaunchConfig_t cfg = {};
        cfg.gridDim = dim3(352); cfg.blockDim = dim3(256);
        cfg.dynamicSmemBytes = smemB;
        cfg.attrs = attr; cfg.numAttrs = 1;
        cudaLaunchKernelEx(&cfg, k_attn, a2a);
    }
    {   // k_final with PDL
        cudaLaunchConfig_t cfg = {};
        cfg.gridDim = dim3(512); cfg.blockDim = dim3(256);
        cfg.dynamicSmemBytes = 0;
        cfg.attrs = attr; cfg.numAttrs = 1;
        cudaLaunchKernelEx(&cfg, k_final, x, wf, out);
    }
}